// round 3
// baseline (speedup 1.0000x reference)
#include <cuda_runtime.h>
#include <cuda_bf16.h>

#define N_NODES 100000
#define N_EDGES 500000
#define HIDDEN 32
#define HEADS 4
#define PROJ 128   // HIDDEN*HEADS
#define LN_EPS 1e-5f

// ---------------- scratch (static device globals; no runtime alloc) ----------
__device__ float  g_seg16[N_NODES * 16];   // per-node accumulated w-vector [N,16]
__device__ float4 g_pos4[N_NODES];         // padded positions (16B aligned gather)

// ---------------- init: zero accumulator + pad positions ---------------------
__global__ void __launch_bounds__(256) init_kernel(const float* __restrict__ pos) {
    int node = blockIdx.x * blockDim.x + threadIdx.x;
    if (node >= N_NODES) return;
    float4 z = make_float4(0.f, 0.f, 0.f, 0.f);
    float4* segp = (float4*)&g_seg16[(size_t)node * 16];
    segp[0] = z; segp[1] = z; segp[2] = z; segp[3] = z;
    g_pos4[node] = make_float4(pos[3 * node + 0], pos[3 * node + 1], pos[3 * node + 2], 0.f);
}

// ---------------- edge kernel: in-block prep + scores -> softmax -> scatter ---
// Per-block redundant prep (inputs are L2-broadcast cached):
//   threads 0..63  : scoreC entries  (A[9], u[3], s per head, /sqrt(32))
//   threads 64..127: int64-vs-int32 detect on first 64 odd words
__global__ void __launch_bounds__(256) edge_kernel(const void* __restrict__ ei_raw,
                                                   const float* __restrict__ Wq,
                                                   const float* __restrict__ bq,
                                                   const float* __restrict__ Wk,
                                                   const float* __restrict__ bk) {
    __shared__ __align__(16) float sSc[64];
    __shared__ int s_nz;
    int t = threadIdx.x;
    if (t == 64) s_nz = 0;
    __syncthreads();

    if (t < 64) {
        const float invs = 0.17677669529663687f;  // 1/sqrt(32)
        int h = t >> 4;
        int idx = t & 15;
        float acc = 0.f;
        if (idx < 9) {
            int i = idx / 3, j = idx % 3;
#pragma unroll 8
            for (int d = 0; d < 32; d++)
                acc += __ldg(&Wq[i * PROJ + h * 32 + d]) * __ldg(&Wk[j * PROJ + h * 32 + d]);
        } else if (idx < 12) {
            int i = idx - 9;
#pragma unroll 8
            for (int d = 0; d < 32; d++)
                acc += __ldg(&Wq[i * PROJ + h * 32 + d]) * __ldg(&bk[h * 32 + d])
                     + __ldg(&Wk[i * PROJ + h * 32 + d]) * __ldg(&bq[h * 32 + d]);
        } else if (idx == 12) {
#pragma unroll 8
            for (int d = 0; d < 32; d++)
                acc += __ldg(&bq[h * 32 + d]) * __ldg(&bk[h * 32 + d]);
        }
        sSc[t] = acc * invs;
    } else if (t < 128) {
        int v = __ldg(&((const int*)ei_raw)[2 * (t - 64) + 1]);  // first 512B, safe either way
        if (v != 0) atomicOr(&s_nz, 1);
    }
    __syncthreads();
    bool is64 = (s_nz == 0);

    int e = blockIdx.x * blockDim.x + t;
    if (e >= N_EDGES) return;

    int row, col;
    if (is64) {
        const long long* ei = (const long long*)ei_raw;
        row = (int)__ldg(&ei[e]);
        col = (int)__ldg(&ei[N_EDGES + e]);
    } else {
        const int* ei = (const int*)ei_raw;
        row = __ldg(&ei[e]);
        col = __ldg(&ei[N_EDGES + e]);
    }

    float4 pr = g_pos4[row];
    float4 pc = g_pos4[col];
    float x = pr.x - pc.x;
    float y = pr.y - pc.y;
    float z = pr.z - pc.z;

    // scores per head: rel^T A rel + u.rel + s   (already scaled by 1/sqrt(32))
    float sc[HEADS];
    float mx = -1e30f;
#pragma unroll
    for (int h = 0; h < HEADS; h++) {
        const float* c = &sSc[16 * h];
        float t0 = c[0] * x + c[1] * y + c[2] * z;
        float t1 = c[3] * x + c[4] * y + c[5] * z;
        float t2 = c[6] * x + c[7] * y + c[8] * z;
        float s = x * t0 + y * t1 + z * t2 + c[9] * x + c[10] * y + c[11] * z + c[12];
        sc[h] = s;
        mx = fmaxf(mx, s);
    }
    float sum = 0.f;
#pragma unroll
    for (int h = 0; h < HEADS; h++) {
        sc[h] = __expf(sc[h] - mx);
        sum += sc[h];
    }
    float inv = 1.f / sum;

    // scatter per head: (a*x, a*y, a*z, a).  Count is implicit: sum_h a = 1.
    float* segp = &g_seg16[(size_t)col * 16];
#pragma unroll
    for (int h = 0; h < HEADS; h++) {
        float a = sc[h] * inv;
        asm volatile("red.global.add.v4.f32 [%0], {%1,%2,%3,%4};"
                     :: "l"(segp + 4 * h), "f"(a * x), "f"(a * y), "f"(a * z), "f"(a)
                     : "memory");
    }
}

// ---------------- node kernel: in-block M prep + fold + mean + LN + SiLU -----
__global__ void __launch_bounds__(256) node_kernel(float* __restrict__ out,
                                                   const float* __restrict__ Wv,
                                                   const float* __restrict__ bv,
                                                   const float* __restrict__ Wout,
                                                   const float* __restrict__ bout,
                                                   const float* __restrict__ gamma,
                                                   const float* __restrict__ beta) {
    __shared__ __align__(16) float sM[512];   // M^T: [d][h*4 + {mx,my,mz,c}]
    __shared__ float sB[32], sG[32], sBe[32];
    int t = threadIdx.x;

    // per-block redundant M compute: thread t does entries t and t+256
#pragma unroll
    for (int rep = 0; rep < 2; rep++) {
        int ent = t + rep * 256;
        int d = ent >> 4;
        int idx = ent & 15;
        int h = idx >> 2;
        int j = idx & 3;
        float acc = 0.f;
        if (j < 3) {
#pragma unroll 8
            for (int dd = 0; dd < 32; dd++)
                acc += __ldg(&Wv[j * PROJ + h * 32 + dd]) * __ldg(&Wout[(h * 32 + dd) * HIDDEN + d]);
        } else {
#pragma unroll 8
            for (int dd = 0; dd < 32; dd++)
                acc += __ldg(&bv[h * 32 + dd]) * __ldg(&Wout[(h * 32 + dd) * HIDDEN + d]);
        }
        sM[ent] = acc;
    }
    if (t < 32) { sB[t] = __ldg(&bout[t]); sG[t] = __ldg(&gamma[t]); sBe[t] = __ldg(&beta[t]); }
    __syncthreads();

    int node = blockIdx.x * blockDim.x + t;
    if (node >= N_NODES) return;

    const float4* Wp = (const float4*)&g_seg16[(size_t)node * 16];
    float4 w0 = Wp[0], w1 = Wp[1], w2 = Wp[2], w3 = Wp[3];
    float cnt = w0.w + w1.w + w2.w + w3.w;          // = exact edge count (sum of attn=1)
    float invc = 1.f / fmaxf(cnt, 1.f);

    const float4* sM4 = (const float4*)sM;
    float o[32];
    float mean = 0.f;
#pragma unroll
    for (int d = 0; d < 32; d++) {
        float4 m0 = sM4[d * 4 + 0];
        float4 m1 = sM4[d * 4 + 1];
        float4 m2 = sM4[d * 4 + 2];
        float4 m3 = sM4[d * 4 + 3];
        float acc = w0.x * m0.x + w0.y * m0.y + w0.z * m0.z + w0.w * m0.w
                  + w1.x * m1.x + w1.y * m1.y + w1.z * m1.z + w1.w * m1.w
                  + w2.x * m2.x + w2.y * m2.y + w2.z * m2.z + w2.w * m2.w
                  + w3.x * m3.x + w3.y * m3.y + w3.z * m3.z + w3.w * m3.w;
        o[d] = acc * invc + sB[d];
        mean += o[d];
    }
    mean *= (1.f / 32.f);
    float var = 0.f;
#pragma unroll
    for (int d = 0; d < 32; d++) {
        float dd = o[d] - mean;
        var += dd * dd;
    }
    float rstd = rsqrtf(var * (1.f / 32.f) + LN_EPS);

    float4* outp = (float4*)&out[(size_t)node * 32];
#pragma unroll
    for (int d4 = 0; d4 < 8; d4++) {
        float4 r;
        float y0 = (o[d4*4+0] - mean) * rstd * sG[d4*4+0] + sBe[d4*4+0];
        float y1 = (o[d4*4+1] - mean) * rstd * sG[d4*4+1] + sBe[d4*4+1];
        float y2 = (o[d4*4+2] - mean) * rstd * sG[d4*4+2] + sBe[d4*4+2];
        float y3 = (o[d4*4+3] - mean) * rstd * sG[d4*4+3] + sBe[d4*4+3];
        r.x = y0 / (1.f + __expf(-y0));
        r.y = y1 / (1.f + __expf(-y1));
        r.z = y2 / (1.f + __expf(-y2));
        r.w = y3 / (1.f + __expf(-y3));
        outp[d4] = r;
    }
}

// ---------------- launch ------------------------------------------------------
extern "C" void kernel_launch(void* const* d_in, const int* in_sizes, int n_in,
                              void* d_out, int out_size) {
    const float* pos  = (const float*)d_in[0];
    const void*  ei   = d_in[1];
    const float* Wq   = (const float*)d_in[2];
    const float* bq   = (const float*)d_in[3];
    const float* Wk   = (const float*)d_in[4];
    const float* bk   = (const float*)d_in[5];
    const float* Wv   = (const float*)d_in[6];
    const float* bv   = (const float*)d_in[7];
    const float* Wout = (const float*)d_in[8];
    const float* bout = (const float*)d_in[9];
    const float* gamma= (const float*)d_in[10];
    const float* beta = (const float*)d_in[11];

    init_kernel<<<(N_NODES + 255) / 256, 256>>>(pos);
    edge_kernel<<<(N_EDGES + 255) / 256, 256>>>(ei, Wq, bq, Wk, bk);
    node_kernel<<<(N_NODES + 255) / 256, 256>>>((float*)d_out, Wv, bv, Wout, bout, gamma, beta);
}

// round 4
// speedup vs baseline: 1.7418x; 1.7418x over previous
#include <cuda_runtime.h>
#include <cuda_bf16.h>

#define N_NODES 100000
#define N_EDGES 500000
#define HIDDEN 32
#define HEADS 4
#define PROJ 128   // HIDDEN*HEADS
#define LN_EPS 1e-5f

#define INIT_BLOCKS ((N_NODES + 255) / 256)   // 391
#define TOTAL_INIT_GRID (INIT_BLOCKS + 3)     // +3 prep blocks

// ---------------- scratch (static device globals; no runtime alloc) ----------
__device__ float  g_seg16[N_NODES * 16];   // per-node accumulated w-vector [N,16]
__device__ float4 g_pos4[N_NODES];         // padded positions (16B aligned gather)
__device__ float  g_scoreC[HEADS * 16];    // per head: A[9], u[3], s, pad3 (all /sqrt(32))
__device__ float  g_M[HIDDEN * 16];        // M^T: [d][h*4 + {mx,my,mz,c}]
__device__ int    g_is64;                  // 1 if edge_index is int64

// ------ fused init: zero accumulator + pack pos4 + (3 tail blocks) prep ------
__global__ void __launch_bounds__(256) init_kernel(const float* __restrict__ pos,
                                                   const float* __restrict__ Wq,
                                                   const float* __restrict__ bq,
                                                   const float* __restrict__ Wk,
                                                   const float* __restrict__ bk,
                                                   const float* __restrict__ Wv,
                                                   const float* __restrict__ bv,
                                                   const float* __restrict__ Wout,
                                                   const int* __restrict__ ei32) {
    if (blockIdx.x < INIT_BLOCKS) {
        int node = blockIdx.x * blockDim.x + threadIdx.x;
        if (node >= N_NODES) return;
        float px = pos[3 * node + 0];
        float py = pos[3 * node + 1];
        float pz = pos[3 * node + 2];
        float4 z = make_float4(0.f, 0.f, 0.f, 0.f);
        float4* segp = (float4*)&g_seg16[(size_t)node * 16];
        segp[0] = z; segp[1] = z; segp[2] = z; segp[3] = z;
        g_pos4[node] = make_float4(px, py, pz, 0.f);
        return;
    }

    // ---- prep blocks: t in [0, 768) across 3 blocks ----
    const float invs = 0.17677669529663687f;  // 1/sqrt(32)
    int t = (blockIdx.x - INIT_BLOCKS) * 256 + threadIdx.x;

    if (t < 512) {
        // M^T entries: g_M[d*16 + h*4 + j]
        int d = t >> 4;
        int idx = t & 15;
        int h = idx >> 2;
        int j = idx & 3;
        float acc = 0.f;
        if (j < 3) {
#pragma unroll 8
            for (int dd = 0; dd < 32; dd++)
                acc += Wv[j * PROJ + h * 32 + dd] * Wout[(h * 32 + dd) * HIDDEN + d];
        } else {
#pragma unroll 8
            for (int dd = 0; dd < 32; dd++)
                acc += bv[h * 32 + dd] * Wout[(h * 32 + dd) * HIDDEN + d];
        }
        g_M[t] = acc;
    } else if (t < 576) {
        int u = t - 512;
        int h = u >> 4;
        int idx = u & 15;
        float acc = 0.f;
        if (idx < 9) {
            int i = idx / 3, j = idx % 3;
#pragma unroll 8
            for (int d = 0; d < 32; d++)
                acc += Wq[i * PROJ + h * 32 + d] * Wk[j * PROJ + h * 32 + d];
        } else if (idx < 12) {
            int i = idx - 9;
#pragma unroll 8
            for (int d = 0; d < 32; d++)
                acc += Wq[i * PROJ + h * 32 + d] * bk[h * 32 + d]
                     + Wk[i * PROJ + h * 32 + d] * bq[h * 32 + d];
        } else if (idx == 12) {
#pragma unroll 8
            for (int d = 0; d < 32; d++)
                acc += bq[h * 32 + d] * bk[h * 32 + d];
        }
        g_scoreC[u] = acc * invs;
    } else if (t >= 576 && t < 608) {
        // int64 detect: one full warp scans first 256 odd 32-bit words (2KB).
        int lane = t - 576;
        int acc = 0;
#pragma unroll
        for (int i = 0; i < 8; i++)
            acc |= ei32[2 * (lane * 8 + i) + 1];
        unsigned m = __ballot_sync(0xffffffffu, acc != 0);
        if (lane == 0) g_is64 = (m == 0) ? 1 : 0;
    }
}

// ---------------- edge kernel: scores -> softmax -> 16-float scatter ----------
__global__ void __launch_bounds__(256) edge_kernel(const void* __restrict__ ei_raw) {
    __shared__ __align__(16) float sSc[64];
    int t = threadIdx.x;
    if (t < 64) sSc[t] = g_scoreC[t];
    __syncthreads();

    int e = blockIdx.x * blockDim.x + t;
    if (e >= N_EDGES) return;

    int row, col;
    if (g_is64) {
        const long long* ei = (const long long*)ei_raw;
        row = (int)__ldg(&ei[e]);
        col = (int)__ldg(&ei[N_EDGES + e]);
    } else {
        const int* ei = (const int*)ei_raw;
        row = __ldg(&ei[e]);
        col = __ldg(&ei[N_EDGES + e]);
    }

    float4 pr = g_pos4[row];
    float4 pc = g_pos4[col];
    float x = pr.x - pc.x;
    float y = pr.y - pc.y;
    float z = pr.z - pc.z;

    // scores per head: rel^T A rel + u.rel + s   (already scaled by 1/sqrt(32))
    float sc[HEADS];
    float mx = -1e30f;
#pragma unroll
    for (int h = 0; h < HEADS; h++) {
        const float* c = &sSc[16 * h];
        float t0 = c[0] * x + c[1] * y + c[2] * z;
        float t1 = c[3] * x + c[4] * y + c[5] * z;
        float t2 = c[6] * x + c[7] * y + c[8] * z;
        float s = x * t0 + y * t1 + z * t2 + c[9] * x + c[10] * y + c[11] * z + c[12];
        sc[h] = s;
        mx = fmaxf(mx, s);
    }
    float sum = 0.f;
#pragma unroll
    for (int h = 0; h < HEADS; h++) {
        sc[h] = __expf(sc[h] - mx);
        sum += sc[h];
    }
    float inv = 1.f / sum;

    // scatter per head: (a*x, a*y, a*z, a).  Count is implicit: sum_h a = 1.
    float* segp = &g_seg16[(size_t)col * 16];
#pragma unroll
    for (int h = 0; h < HEADS; h++) {
        float a = sc[h] * inv;
        asm volatile("red.global.add.v4.f32 [%0], {%1,%2,%3,%4};"
                     :: "l"(segp + 4 * h), "f"(a * x), "f"(a * y), "f"(a * z), "f"(a)
                     : "memory");
    }
}

// ---------------- node kernel: thread-per-node fold + mean + LN + SiLU -------
__global__ void __launch_bounds__(256) node_kernel(float* __restrict__ out,
                                                   const float* __restrict__ bout,
                                                   const float* __restrict__ gamma,
                                                   const float* __restrict__ beta) {
    __shared__ __align__(16) float sM[512];   // M^T: [d][16]
    __shared__ float sB[32], sG[32], sBe[32];
    int t = threadIdx.x;
    for (int i = t; i < 512; i += blockDim.x) sM[i] = g_M[i];
    if (t < 32) { sB[t] = __ldg(&bout[t]); sG[t] = __ldg(&gamma[t]); sBe[t] = __ldg(&beta[t]); }
    __syncthreads();

    int node = blockIdx.x * blockDim.x + t;
    if (node >= N_NODES) return;

    const float4* Wp = (const float4*)&g_seg16[(size_t)node * 16];
    float4 w0 = Wp[0], w1 = Wp[1], w2 = Wp[2], w3 = Wp[3];
    float cnt = w0.w + w1.w + w2.w + w3.w;          // exact edge count (sum of attn = 1)
    float invc = 1.f / fmaxf(cnt, 1.f);

    const float4* sM4 = (const float4*)sM;
    float o[32];
    float mean = 0.f;
#pragma unroll
    for (int d = 0; d < 32; d++) {
        float4 m0 = sM4[d * 4 + 0];
        float4 m1 = sM4[d * 4 + 1];
        float4 m2 = sM4[d * 4 + 2];
        float4 m3 = sM4[d * 4 + 3];
        float acc = w0.x * m0.x + w0.y * m0.y + w0.z * m0.z + w0.w * m0.w
                  + w1.x * m1.x + w1.y * m1.y + w1.z * m1.z + w1.w * m1.w
                  + w2.x * m2.x + w2.y * m2.y + w2.z * m2.z + w2.w * m2.w
                  + w3.x * m3.x + w3.y * m3.y + w3.z * m3.z + w3.w * m3.w;
        o[d] = acc * invc + sB[d];
        mean += o[d];
    }
    mean *= (1.f / 32.f);
    float var = 0.f;
#pragma unroll
    for (int d = 0; d < 32; d++) {
        float dd = o[d] - mean;
        var += dd * dd;
    }
    float rstd = rsqrtf(var * (1.f / 32.f) + LN_EPS);

    float4* outp = (float4*)&out[(size_t)node * 32];
#pragma unroll
    for (int d4 = 0; d4 < 8; d4++) {
        float4 r;
        float y0 = (o[d4*4+0] - mean) * rstd * sG[d4*4+0] + sBe[d4*4+0];
        float y1 = (o[d4*4+1] - mean) * rstd * sG[d4*4+1] + sBe[d4*4+1];
        float y2 = (o[d4*4+2] - mean) * rstd * sG[d4*4+2] + sBe[d4*4+2];
        float y3 = (o[d4*4+3] - mean) * rstd * sG[d4*4+3] + sBe[d4*4+3];
        r.x = y0 / (1.f + __expf(-y0));
        r.y = y1 / (1.f + __expf(-y1));
        r.z = y2 / (1.f + __expf(-y2));
        r.w = y3 / (1.f + __expf(-y3));
        outp[d4] = r;
    }
}

// ---------------- launch ------------------------------------------------------
extern "C" void kernel_launch(void* const* d_in, const int* in_sizes, int n_in,
                              void* d_out, int out_size) {
    const float* pos  = (const float*)d_in[0];
    const void*  ei   = d_in[1];
    const float* Wq   = (const float*)d_in[2];
    const float* bq   = (const float*)d_in[3];
    const float* Wk   = (const float*)d_in[4];
    const float* bk   = (const float*)d_in[5];
    const float* Wv   = (const float*)d_in[6];
    const float* bv   = (const float*)d_in[7];
    const float* Wout = (const float*)d_in[8];
    const float* bout = (const float*)d_in[9];
    const float* gamma= (const float*)d_in[10];
    const float* beta = (const float*)d_in[11];

    init_kernel<<<TOTAL_INIT_GRID, 256>>>(pos, Wq, bq, Wk, bk, Wv, bv, Wout, (const int*)ei);
    edge_kernel<<<(N_EDGES + 255) / 256, 256>>>(ei);
    node_kernel<<<(N_NODES + 255) / 256, 256>>>((float*)d_out, bout, gamma, beta);
}

// round 5
// speedup vs baseline: 1.7689x; 1.0156x over previous
#include <cuda_runtime.h>
#include <cuda_bf16.h>

#define N_NODES 100000
#define N_EDGES 500000
#define HIDDEN 32
#define HEADS 4
#define PROJ 128   // HIDDEN*HEADS
#define LN_EPS 1e-5f

#define POS_BLOCKS ((N_NODES + 255) / 256)    // 391
#define INIT_GRID (POS_BLOCKS + 3)            // 3 prep blocks lead (blockIdx 0..2)

// ---------------- scratch (static device globals; no runtime alloc) ----------
// g_seg16 starts zero (module-load zero-init); node_kernel re-zeros it after
// reading, so every kernel_launch sees zeros without a memset on the path.
__device__ float  g_seg16[N_NODES * 16];   // per-node accumulated w-vector [N,16]
__device__ float4 g_pos4[N_NODES];         // padded positions (16B aligned gather)
__device__ float  g_scoreC[HEADS * 16];    // per head: A[9], u[3], s, pad3 (all /sqrt(32))
__device__ float  g_M[HIDDEN * 16];        // M^T: [d][h*4 + {mx,my,mz,c}]
__device__ int    g_is64;                  // 1 if edge_index is int64

// ------ fused init: (blocks 0..2) prep + (rest) pack pos4 --------------------
__global__ void __launch_bounds__(256) init_kernel(const float* __restrict__ pos,
                                                   const float* __restrict__ Wq,
                                                   const float* __restrict__ bq,
                                                   const float* __restrict__ Wk,
                                                   const float* __restrict__ bk,
                                                   const float* __restrict__ Wv,
                                                   const float* __restrict__ bv,
                                                   const float* __restrict__ Wout,
                                                   const int* __restrict__ ei32) {
    if (blockIdx.x >= 3) {
        int node = (blockIdx.x - 3) * blockDim.x + threadIdx.x;
        if (node >= N_NODES) return;
        float px = pos[3 * node + 0];
        float py = pos[3 * node + 1];
        float pz = pos[3 * node + 2];
        g_pos4[node] = make_float4(px, py, pz, 0.f);
        return;
    }

    // ---- prep blocks: t in [0, 768) ----
    const float invs = 0.17677669529663687f;  // 1/sqrt(32)
    int t = blockIdx.x * 256 + threadIdx.x;

    if (t < 512) {
        // M^T entries: g_M[d*16 + h*4 + j]
        int d = t >> 4;
        int idx = t & 15;
        int h = idx >> 2;
        int j = idx & 3;
        float acc = 0.f;
        if (j < 3) {
#pragma unroll 8
            for (int dd = 0; dd < 32; dd++)
                acc += Wv[j * PROJ + h * 32 + dd] * Wout[(h * 32 + dd) * HIDDEN + d];
        } else {
#pragma unroll 8
            for (int dd = 0; dd < 32; dd++)
                acc += bv[h * 32 + dd] * Wout[(h * 32 + dd) * HIDDEN + d];
        }
        g_M[t] = acc;
    } else if (t < 576) {
        int u = t - 512;
        int h = u >> 4;
        int idx = u & 15;
        float acc = 0.f;
        if (idx < 9) {
            int i = idx / 3, j = idx % 3;
#pragma unroll 8
            for (int d = 0; d < 32; d++)
                acc += Wq[i * PROJ + h * 32 + d] * Wk[j * PROJ + h * 32 + d];
        } else if (idx < 12) {
            int i = idx - 9;
#pragma unroll 8
            for (int d = 0; d < 32; d++)
                acc += Wq[i * PROJ + h * 32 + d] * bk[h * 32 + d]
                     + Wk[i * PROJ + h * 32 + d] * bq[h * 32 + d];
        } else if (idx == 12) {
#pragma unroll 8
            for (int d = 0; d < 32; d++)
                acc += bq[h * 32 + d] * bk[h * 32 + d];
        }
        g_scoreC[u] = acc * invs;
    } else if (t >= 576 && t < 608) {
        // int64 detect: one warp scans first 256 odd 32-bit words (2KB).
        int lane = t - 576;
        int acc = 0;
#pragma unroll
        for (int i = 0; i < 8; i++)
            acc |= ei32[2 * (lane * 8 + i) + 1];
        unsigned m = __ballot_sync(0xffffffffu, acc != 0);
        if (lane == 0) g_is64 = (m == 0) ? 1 : 0;
    }
}

// ------------- edge kernel: 2 edges/thread, scores -> softmax -> scatter -----
__device__ __forceinline__ void edge_body(int row, int col, const float* sSc) {
    float4 pr = g_pos4[row];
    float4 pc = g_pos4[col];
    float x = pr.x - pc.x;
    float y = pr.y - pc.y;
    float z = pr.z - pc.z;

    float sc[HEADS];
    float mx = -1e30f;
#pragma unroll
    for (int h = 0; h < HEADS; h++) {
        const float* c = &sSc[16 * h];
        float t0 = c[0] * x + c[1] * y + c[2] * z;
        float t1 = c[3] * x + c[4] * y + c[5] * z;
        float t2 = c[6] * x + c[7] * y + c[8] * z;
        float s = x * t0 + y * t1 + z * t2 + c[9] * x + c[10] * y + c[11] * z + c[12];
        sc[h] = s;
        mx = fmaxf(mx, s);
    }
    float sum = 0.f;
#pragma unroll
    for (int h = 0; h < HEADS; h++) {
        sc[h] = __expf(sc[h] - mx);
        sum += sc[h];
    }
    float inv = 1.f / sum;

    float* segp = &g_seg16[(size_t)col * 16];
#pragma unroll
    for (int h = 0; h < HEADS; h++) {
        float a = sc[h] * inv;
        asm volatile("red.global.add.v4.f32 [%0], {%1,%2,%3,%4};"
                     :: "l"(segp + 4 * h), "f"(a * x), "f"(a * y), "f"(a * z), "f"(a)
                     : "memory");
    }
}

__global__ void __launch_bounds__(256) edge_kernel(const void* __restrict__ ei_raw) {
    __shared__ __align__(16) float sSc[64];
    int t = threadIdx.x;
    if (t < 64) sSc[t] = g_scoreC[t];
    __syncthreads();

    int pair = blockIdx.x * blockDim.x + t;
    if (pair >= N_EDGES / 2) return;
    int e0 = 2 * pair;

    int row0, col0, row1, col1;
    if (g_is64) {
        const longlong2* eiR = (const longlong2*)ei_raw;             // rows at [0]
        const longlong2* eiC = (const longlong2*)((const long long*)ei_raw + N_EDGES);
        longlong2 r = __ldg(&eiR[pair]);
        longlong2 c = __ldg(&eiC[pair]);
        row0 = (int)r.x; row1 = (int)r.y;
        col0 = (int)c.x; col1 = (int)c.y;
    } else {
        const int2* eiR = (const int2*)ei_raw;
        const int2* eiC = (const int2*)((const int*)ei_raw + N_EDGES);
        int2 r = __ldg(&eiR[pair]);
        int2 c = __ldg(&eiC[pair]);
        row0 = r.x; row1 = r.y;
        col0 = c.x; col1 = c.y;
    }

    edge_body(row0, col0, sSc);
    edge_body(row1, col1, sSc);
}

// ------- node kernel: fold + mean + LN + SiLU; re-zeros g_seg16 --------------
__global__ void __launch_bounds__(256) node_kernel(float* __restrict__ out,
                                                   const float* __restrict__ bout,
                                                   const float* __restrict__ gamma,
                                                   const float* __restrict__ beta) {
    __shared__ __align__(16) float sM[512];   // M^T: [d][16]
    __shared__ float sB[32], sG[32], sBe[32];
    int t = threadIdx.x;
    for (int i = t; i < 512; i += blockDim.x) sM[i] = g_M[i];
    if (t < 32) { sB[t] = __ldg(&bout[t]); sG[t] = __ldg(&gamma[t]); sBe[t] = __ldg(&beta[t]); }
    __syncthreads();

    int node = blockIdx.x * blockDim.x + t;
    if (node >= N_NODES) return;

    float4* Wp = (float4*)&g_seg16[(size_t)node * 16];
    float4 w0 = Wp[0], w1 = Wp[1], w2 = Wp[2], w3 = Wp[3];
    // restore the zero-state invariant for the next launch/replay
    float4 z = make_float4(0.f, 0.f, 0.f, 0.f);
    Wp[0] = z; Wp[1] = z; Wp[2] = z; Wp[3] = z;

    float cnt = w0.w + w1.w + w2.w + w3.w;          // exact edge count (sum of attn = 1)
    float invc = 1.f / fmaxf(cnt, 1.f);

    const float4* sM4 = (const float4*)sM;
    float o[32];
    float mean = 0.f;
#pragma unroll
    for (int d = 0; d < 32; d++) {
        float4 m0 = sM4[d * 4 + 0];
        float4 m1 = sM4[d * 4 + 1];
        float4 m2 = sM4[d * 4 + 2];
        float4 m3 = sM4[d * 4 + 3];
        float acc = w0.x * m0.x + w0.y * m0.y + w0.z * m0.z + w0.w * m0.w
                  + w1.x * m1.x + w1.y * m1.y + w1.z * m1.z + w1.w * m1.w
                  + w2.x * m2.x + w2.y * m2.y + w2.z * m2.z + w2.w * m2.w
                  + w3.x * m3.x + w3.y * m3.y + w3.z * m3.z + w3.w * m3.w;
        o[d] = acc * invc + sB[d];
        mean += o[d];
    }
    mean *= (1.f / 32.f);
    float var = 0.f;
#pragma unroll
    for (int d = 0; d < 32; d++) {
        float dd = o[d] - mean;
        var += dd * dd;
    }
    float rstd = rsqrtf(var * (1.f / 32.f) + LN_EPS);

    float4* outp = (float4*)&out[(size_t)node * 32];
#pragma unroll
    for (int d4 = 0; d4 < 8; d4++) {
        float4 r;
        float y0 = (o[d4*4+0] - mean) * rstd * sG[d4*4+0] + sBe[d4*4+0];
        float y1 = (o[d4*4+1] - mean) * rstd * sG[d4*4+1] + sBe[d4*4+1];
        float y2 = (o[d4*4+2] - mean) * rstd * sG[d4*4+2] + sBe[d4*4+2];
        float y3 = (o[d4*4+3] - mean) * rstd * sG[d4*4+3] + sBe[d4*4+3];
        r.x = y0 / (1.f + __expf(-y0));
        r.y = y1 / (1.f + __expf(-y1));
        r.z = y2 / (1.f + __expf(-y2));
        r.w = y3 / (1.f + __expf(-y3));
        outp[d4] = r;
    }
}

// ---------------- launch ------------------------------------------------------
extern "C" void kernel_launch(void* const* d_in, const int* in_sizes, int n_in,
                              void* d_out, int out_size) {
    const float* pos  = (const float*)d_in[0];
    const void*  ei   = d_in[1];
    const float* Wq   = (const float*)d_in[2];
    const float* bq   = (const float*)d_in[3];
    const float* Wk   = (const float*)d_in[4];
    const float* bk   = (const float*)d_in[5];
    const float* Wv   = (const float*)d_in[6];
    const float* bv   = (const float*)d_in[7];
    const float* Wout = (const float*)d_in[8];
    const float* bout = (const float*)d_in[9];
    const float* gamma= (const float*)d_in[10];
    const float* beta = (const float*)d_in[11];

    init_kernel<<<INIT_GRID, 256>>>(pos, Wq, bq, Wk, bk, Wv, bv, Wout, (const int*)ei);
    edge_kernel<<<(N_EDGES / 2 + 255) / 256, 256>>>(ei);
    node_kernel<<<(N_NODES + 255) / 256, 256>>>((float*)d_out, bout, gamma, beta);
}